// round 4
// baseline (speedup 1.0000x reference)
#include <cuda_runtime.h>
#include <math.h>
#include <stdint.h>

// Problem dims
#define BD   2
#define TD   2048
#define CD   1024
#define HN   16
#define HD   64
#define DFFD 4096
#define NT   (BD * TD)   // 4096 tokens

// ---------------------------------------------------------------------------
// Scratch
// ---------------------------------------------------------------------------
__device__ float g_t  [(size_t)NT * CD];
__device__ float g_q  [(size_t)NT * CD];
__device__ float g_k  [(size_t)NT * CD];
__device__ float g_v  [(size_t)NT * CD];
__device__ float g_ctx[(size_t)NT * CD];
__device__ float g_x2 [(size_t)NT * CD];
__device__ float g_h  [(size_t)NT * DFFD];

// ---------------------------------------------------------------------------
// Helpers
// ---------------------------------------------------------------------------
__device__ __forceinline__ uint32_t f2tf32(float f) {
    uint32_t u;
    asm("cvt.rna.tf32.f32 %0, %1;" : "=r"(u) : "f"(f));
    return u;
}
__device__ __forceinline__ void cp16(uint32_t smem_dst, const void* gptr) {
    asm volatile("cp.async.cg.shared.global [%0], [%1], 16;\n"
                 :: "r"(smem_dst), "l"(gptr));
}
__device__ __forceinline__ void cp_commit() {
    asm volatile("cp.async.commit_group;\n" ::: "memory");
}
template <int N>
__device__ __forceinline__ void cp_wait() {
    asm volatile("cp.async.wait_group %0;\n" :: "n"(N) : "memory");
}
__device__ __forceinline__ void mma_tf32(float* c, const uint32_t* a, const uint32_t* b) {
    asm volatile(
        "mma.sync.aligned.m16n8k8.row.col.f32.tf32.tf32.f32 "
        "{%0,%1,%2,%3},{%4,%5,%6,%7},{%8,%9},{%0,%1,%2,%3};"
        : "+f"(c[0]), "+f"(c[1]), "+f"(c[2]), "+f"(c[3])
        : "r"(a[0]), "r"(a[1]), "r"(a[2]), "r"(a[3]), "r"(b[0]), "r"(b[1]));
}

// ---------------------------------------------------------------------------
// Fused double LayerNorm
// ---------------------------------------------------------------------------
__global__ __launch_bounds__(256) void ln2_kernel(
    const float* __restrict__ x,
    const float* __restrict__ ga, const float* __restrict__ ba,
    const float* __restrict__ gb, const float* __restrict__ bb,
    float* __restrict__ out)
{
    __shared__ float red[16];
    __shared__ float bc[2];
    const int row = blockIdx.x, tid = threadIdx.x;
    const float4 v = *(const float4*)(x + (size_t)row * CD + tid * 4);

    float s  = v.x + v.y + v.z + v.w;
    float s2 = v.x*v.x + v.y*v.y + v.z*v.z + v.w*v.w;
    #pragma unroll
    for (int o = 16; o; o >>= 1) {
        s  += __shfl_xor_sync(~0u, s,  o);
        s2 += __shfl_xor_sync(~0u, s2, o);
    }
    if ((tid & 31) == 0) { red[(tid >> 5)*2] = s; red[(tid >> 5)*2 + 1] = s2; }
    __syncthreads();
    if (tid == 0) {
        float a = 0.f, b2 = 0.f;
        #pragma unroll
        for (int w = 0; w < 8; w++) { a += red[w*2]; b2 += red[w*2 + 1]; }
        float mu  = a * (1.f / CD);
        float var = b2 * (1.f / CD) - mu * mu;
        bc[0] = mu; bc[1] = rsqrtf(var + 1e-5f);
    }
    __syncthreads();
    float mu = bc[0], rstd = bc[1];
    __syncthreads();

    const float4 g4 = *(const float4*)(ga + tid * 4);
    const float4 b4 = *(const float4*)(ba + tid * 4);
    float y[4];
    y[0] = (v.x - mu) * rstd * g4.x + b4.x;
    y[1] = (v.y - mu) * rstd * g4.y + b4.y;
    y[2] = (v.z - mu) * rstd * g4.z + b4.z;
    y[3] = (v.w - mu) * rstd * g4.w + b4.w;

    s  = y[0] + y[1] + y[2] + y[3];
    s2 = y[0]*y[0] + y[1]*y[1] + y[2]*y[2] + y[3]*y[3];
    #pragma unroll
    for (int o = 16; o; o >>= 1) {
        s  += __shfl_xor_sync(~0u, s,  o);
        s2 += __shfl_xor_sync(~0u, s2, o);
    }
    if ((tid & 31) == 0) { red[(tid >> 5)*2] = s; red[(tid >> 5)*2 + 1] = s2; }
    __syncthreads();
    if (tid == 0) {
        float a = 0.f, b2 = 0.f;
        #pragma unroll
        for (int w = 0; w < 8; w++) { a += red[w*2]; b2 += red[w*2 + 1]; }
        float mu2  = a * (1.f / CD);
        float var2 = b2 * (1.f / CD) - mu2 * mu2;
        bc[0] = mu2; bc[1] = rsqrtf(var2 + 1e-5f);
    }
    __syncthreads();
    mu = bc[0]; rstd = bc[1];

    const float4 g24 = *(const float4*)(gb + tid * 4);
    const float4 b24 = *(const float4*)(bb + tid * 4);
    float4 o;
    o.x = (y[0] - mu) * rstd * g24.x + b24.x;
    o.y = (y[1] - mu) * rstd * g24.y + b24.y;
    o.z = (y[2] - mu) * rstd * g24.z + b24.z;
    o.w = (y[3] - mu) * rstd * g24.w + b24.w;
    *(float4*)(out + (size_t)row * CD + tid * 4) = o;
}

__global__ __launch_bounds__(256) void ln1_kernel(
    const float* __restrict__ x,
    const float* __restrict__ g, const float* __restrict__ b,
    float* __restrict__ out)
{
    __shared__ float red[16];
    __shared__ float bc[2];
    const int row = blockIdx.x, tid = threadIdx.x;
    const float4 v = *(const float4*)(x + (size_t)row * CD + tid * 4);

    float s  = v.x + v.y + v.z + v.w;
    float s2 = v.x*v.x + v.y*v.y + v.z*v.z + v.w*v.w;
    #pragma unroll
    for (int o = 16; o; o >>= 1) {
        s  += __shfl_xor_sync(~0u, s,  o);
        s2 += __shfl_xor_sync(~0u, s2, o);
    }
    if ((tid & 31) == 0) { red[(tid >> 5)*2] = s; red[(tid >> 5)*2 + 1] = s2; }
    __syncthreads();
    if (tid == 0) {
        float a = 0.f, b2 = 0.f;
        #pragma unroll
        for (int w = 0; w < 8; w++) { a += red[w*2]; b2 += red[w*2 + 1]; }
        float mu  = a * (1.f / CD);
        float var = b2 * (1.f / CD) - mu * mu;
        bc[0] = mu; bc[1] = rsqrtf(var + 1e-5f);
    }
    __syncthreads();
    const float mu = bc[0], rstd = bc[1];
    const float4 g4 = *(const float4*)(g + tid * 4);
    const float4 b4 = *(const float4*)(b + tid * 4);
    float4 o;
    o.x = (v.x - mu) * rstd * g4.x + b4.x;
    o.y = (v.y - mu) * rstd * g4.y + b4.y;
    o.z = (v.z - mu) * rstd * g4.z + b4.z;
    o.w = (v.w - mu) * rstd * g4.w + b4.w;
    *(float4*)(out + (size_t)row * CD + tid * 4) = o;
}

// ---------------------------------------------------------------------------
// TF32 tensor-core GEMM v2: 128x256 block tile, BK=16, 8 warps (2x4),
// warp tile 64x64. A operand cvt.rna, B raw-bit truncation.
//   A smem: [m][k'] k' = k ^ (4*((m>>1)&3)), row stride 16
//   B smem: [k][n'] n' = n ^ (8*k),          row stride 256
// ---------------------------------------------------------------------------
#define BMT 128
#define BNT 256

__global__ __launch_bounds__(256, 1) void gemm_tc(
    const float* __restrict__ A, const float* __restrict__ W,
    const float* __restrict__ bias, const float* __restrict__ res,
    float* __restrict__ Cc, int M, int N, int K, int act)
{
    __shared__ float As[2][BMT * 16];   // 2 x 8 KB
    __shared__ float Bs[2][16 * BNT];   // 2 x 16 KB  (total 48 KB)

    const int tid  = threadIdx.x;
    const int lane = tid & 31;
    const int warp = tid >> 5;
    const int wm = warp & 1;        // 0..1  (64 rows)
    const int wn = warp >> 1;       // 0..3  (64 cols)
    const int bm = blockIdx.y * BMT;
    const int bn = blockIdx.x * BNT;

    const uint32_t sA = (uint32_t)__cvta_generic_to_shared(&As[0][0]);
    const uint32_t sB = (uint32_t)__cvta_generic_to_shared(&Bs[0][0]);

    // cp.async assignment: A 512 chunks (2/thread), B 1024 chunks (4/thread)
    const int am  = (tid + 0)   >> 2,  ak  = (tid + 0)   & 3;
    const int am2 = (tid + 256) >> 2,  ak2 = (tid + 256) & 3;

    float acc[4][8][4];
    #pragma unroll
    for (int i = 0; i < 4; i++)
        #pragma unroll
        for (int j = 0; j < 8; j++)
            #pragma unroll
            for (int r = 0; r < 4; r++) acc[i][j][r] = 0.f;

    auto issue = [&](int s, int k0) {
        // A
        uint32_t d = sA + (uint32_t)(s * (BMT*16) + am * 16 + ((ak * 4) ^ (4 * ((am >> 1) & 3)))) * 4u;
        cp16(d, A + (size_t)(bm + am) * K + k0 + ak * 4);
        uint32_t d2 = sA + (uint32_t)(s * (BMT*16) + am2 * 16 + ((ak2 * 4) ^ (4 * ((am2 >> 1) & 3)))) * 4u;
        cp16(d2, A + (size_t)(bm + am2) * K + k0 + ak2 * 4);
        // B: 4 chunks per thread
        #pragma unroll
        for (int c = 0; c < 4; c++) {
            const int idx = tid + c * 256;       // 0..1023
            const int bkr = idx >> 6;            // row 0..15
            const int bcc = idx & 63;            // chunk col 0..63
            uint32_t db = sB + (uint32_t)(s * (16*BNT) + bkr * BNT + ((bcc * 4) ^ (8 * bkr))) * 4u;
            cp16(db, W + (size_t)(k0 + bkr) * N + bn + bcc * 4);
        }
    };

    issue(0, 0);  cp_commit();
    issue(1, 16); cp_commit();

    const int nK = K >> 4;
    const int r4 = lane >> 2;   // 0..7
    const int c4 = lane & 3;    // 0..3

    for (int kt = 0; kt < nK; kt++) {
        cp_wait<1>();
        __syncthreads();
        const int cur = kt & 1;
        const float* Ap = &As[cur][0];
        const float* Bp = &Bs[cur][0];

        #pragma unroll
        for (int k8 = 0; k8 < 2; k8++) {
            const int kb = k8 * 8 + c4;
            uint32_t af[4][4], bf[8][2];
            #pragma unroll
            for (int mf = 0; mf < 4; mf++) {
                const int m0 = wm * 64 + mf * 16 + r4;
                const int xm = 4 * ((m0 >> 1) & 3);
                const float* p = Ap + m0 * 16;
                af[mf][0] = f2tf32(p[kb ^ xm]);
                af[mf][1] = f2tf32(p[128 + (kb ^ xm)]);
                af[mf][2] = f2tf32(p[(kb + 4) ^ xm]);
                af[mf][3] = f2tf32(p[128 + ((kb + 4) ^ xm)]);
            }
            #pragma unroll
            for (int nf = 0; nf < 8; nf++) {
                const int n = wn * 64 + nf * 8 + r4;
                bf[nf][0] = __float_as_uint(Bp[kb * BNT + (n ^ (8 * kb))]);
                bf[nf][1] = __float_as_uint(Bp[(kb + 4) * BNT + (n ^ (8 * (kb + 4)))]);
            }
            #pragma unroll
            for (int mf = 0; mf < 4; mf++)
                #pragma unroll
                for (int nf = 0; nf < 8; nf++)
                    mma_tf32(acc[mf][nf], af[mf], bf[nf]);
        }
        __syncthreads();
        const int knext = (kt + 2) << 4;
        if (knext < K) issue(cur, knext);
        cp_commit();
    }

    // epilogue
    #pragma unroll
    for (int mf = 0; mf < 4; mf++) {
        #pragma unroll
        for (int nf = 0; nf < 8; nf++) {
            const int col = bn + wn * 64 + nf * 8 + c4 * 2;
            const float bx = bias[col], by = bias[col + 1];
            #pragma unroll
            for (int h = 0; h < 2; h++) {
                const int row = bm + wm * 64 + mf * 16 + r4 + h * 8;
                float ox = acc[mf][nf][h * 2 + 0] + bx;
                float oy = acc[mf][nf][h * 2 + 1] + by;
                if (act) {
                    ox *= 1.f / (1.f + __expf(-ox));
                    oy *= 1.f / (1.f + __expf(-oy));
                }
                const size_t off = (size_t)row * N + col;
                if (res) {
                    const float2 rr = *(const float2*)(res + off);
                    ox += rr.x; oy += rr.y;
                }
                float2 o; o.x = ox; o.y = oy;
                *(float2*)(Cc + off) = o;
            }
        }
    }
}

// ---------------------------------------------------------------------------
// Flash attention on tensor cores (unchanged from R3)
// ---------------------------------------------------------------------------
#define PQ 68
#define PV 72
#define ATTN_SMEM ((64*PQ + 2*64*PQ + 2*64*PV + 4*16*PQ) * 4)

__global__ __launch_bounds__(128) void attn_tc(
    const float* __restrict__ Q, const float* __restrict__ Kg,
    const float* __restrict__ Vg, float* __restrict__ O)
{
    extern __shared__ float sm[];
    float* Qs = sm;
    float* Ks = Qs + 64 * PQ;
    float* Vs = Ks + 2 * 64 * PQ;
    float* Ps = Vs + 2 * 64 * PV;

    const int bh = blockIdx.y;
    const int b = bh >> 4, h = bh & 15;
    const int qt = blockIdx.x;
    const int q0 = qt * 64;
    const int tid = threadIdx.x;
    const int lane = tid & 31;
    const int warp = tid >> 5;
    const int r4 = lane >> 2;
    const int c4 = lane & 3;
    const size_t base = (size_t)b * TD * CD + (size_t)h * HD;

    const uint32_t sQ = (uint32_t)__cvta_generic_to_shared(Qs);
    const uint32_t sK = (uint32_t)__cvta_generic_to_shared(Ks);
    const uint32_t sV = (uint32_t)__cvta_generic_to_shared(Vs);

    #pragma unroll
    for (int i = 0; i < 8; i++) {
        const int idx = tid + i * 128;
        const int row = idx >> 4, cc = idx & 15;
        cp16(sQ + (uint32_t)(row * PQ + cc * 4) * 4u,
             Q + base + (size_t)(q0 + row) * CD + cc * 4);
    }
    auto issue_kv = [&](int buf, int k0) {
        #pragma unroll
        for (int i = 0; i < 8; i++) {
            const int idx = tid + i * 128;
            const int row = idx >> 4, cc = idx & 15;
            const size_t g = base + (size_t)(k0 + row) * CD + cc * 4;
            cp16(sK + (uint32_t)(buf * 64 * PQ + row * PQ + cc * 4) * 4u, Kg + g);
            cp16(sV + (uint32_t)(buf * 64 * PV + row * PV + cc * 4) * 4u, Vg + g);
        }
    };
    issue_kv(0, 0);
    cp_commit();
    if (qt >= 1) { issue_kv(1, 64); cp_commit(); }

    uint32_t qf[8][4];
    float oacc[8][4];
    #pragma unroll
    for (int nt = 0; nt < 8; nt++)
        #pragma unroll
        for (int r = 0; r < 4; r++) oacc[nt][r] = 0.f;
    float m0 = -1e30f, m1 = -1e30f, l0 = 0.f, l1 = 0.f;

    float* Pw = Ps + warp * 16 * PQ;

    for (int kt = 0; kt <= qt; kt++) {
        if (kt + 1 <= qt) cp_wait<1>(); else cp_wait<0>();
        __syncthreads();
        const int cur = kt & 1;
        const float* Kp = Ks + cur * 64 * PQ;
        const float* Vp = Vs + cur * 64 * PV;

        if (kt == 0) {
            const float* qp = Qs + (warp * 16 + r4) * PQ;
            #pragma unroll
            for (int ks = 0; ks < 8; ks++) {
                const int c = ks * 8 + c4;
                qf[ks][0] = __float_as_uint(qp[c] * 0.125f);
                qf[ks][1] = __float_as_uint(qp[8 * PQ + c] * 0.125f);
                qf[ks][2] = __float_as_uint(qp[c + 4] * 0.125f);
                qf[ks][3] = __float_as_uint(qp[8 * PQ + c + 4] * 0.125f);
            }
        }

        float sacc[8][4];
        #pragma unroll
        for (int nt = 0; nt < 8; nt++)
            #pragma unroll
            for (int r = 0; r < 4; r++) sacc[nt][r] = 0.f;

        #pragma unroll
        for (int ks = 0; ks < 8; ks++) {
            const int k = ks * 8 + c4;
            #pragma unroll
            for (int nt = 0; nt < 8; nt++) {
                const int n = nt * 8 + r4;
                uint32_t bf[2];
                bf[0] = __float_as_uint(Kp[n * PQ + k]);
                bf[1] = __float_as_uint(Kp[n * PQ + k + 4]);
                mma_tf32(sacc[nt], qf[ks], bf);
            }
        }

        if (kt == qt) {
            const int row0 = warp * 16 + r4;
            #pragma unroll
            for (int nt = 0; nt < 8; nt++) {
                const int cb = nt * 8 + 2 * c4;
                if (cb + 0 > row0)     sacc[nt][0] = -1e30f;
                if (cb + 1 > row0)     sacc[nt][1] = -1e30f;
                if (cb + 0 > row0 + 8) sacc[nt][2] = -1e30f;
                if (cb + 1 > row0 + 8) sacc[nt][3] = -1e30f;
            }
        }

        float rm0 = -1e30f, rm1 = -1e30f;
        #pragma unroll
        for (int nt = 0; nt < 8; nt++) {
            rm0 = fmaxf(rm0, fmaxf(sacc[nt][0], sacc[nt][1]));
            rm1 = fmaxf(rm1, fmaxf(sacc[nt][2], sacc[nt][3]));
        }
        rm0 = fmaxf(rm0, __shfl_xor_sync(~0u, rm0, 1));
        rm0 = fmaxf(rm0, __shfl_xor_sync(~0u, rm0, 2));
        rm1 = fmaxf(rm1, __shfl_xor_sync(~0u, rm1, 1));
        rm1 = fmaxf(rm1, __shfl_xor_sync(~0u, rm1, 2));

        const float mn0 = fmaxf(m0, rm0), mn1 = fmaxf(m1, rm1);
        const float f0 = __expf(m0 - mn0), f1 = __expf(m1 - mn1);
        m0 = mn0; m1 = mn1;

        float rs0 = 0.f, rs1 = 0.f;
        #pragma unroll
        for (int nt = 0; nt < 8; nt++) {
            float p0 = __expf(sacc[nt][0] - mn0);
            float p1 = __expf(sacc[nt][1] - mn0);
            float p2 = __expf(sacc[nt][2] - mn1);
            float p3 = __expf(sacc[nt][3] - mn1);
            rs0 += p0 + p1; rs1 += p2 + p3;
            float2 w0; w0.x = p0; w0.y = p1;
            float2 w1; w1.x = p2; w1.y = p3;
            *(float2*)(Pw + r4 * PQ + nt * 8 + 2 * c4)       = w0;
            *(float2*)(Pw + (r4 + 8) * PQ + nt * 8 + 2 * c4) = w1;
        }
        rs0 += __shfl_xor_sync(~0u, rs0, 1);
        rs0 += __shfl_xor_sync(~0u, rs0, 2);
        rs1 += __shfl_xor_sync(~0u, rs1, 1);
        rs1 += __shfl_xor_sync(~0u, rs1, 2);
        l0 = l0 * f0 + rs0;
        l1 = l1 * f1 + rs1;

        #pragma unroll
        for (int nt = 0; nt < 8; nt++) {
            oacc[nt][0] *= f0; oacc[nt][1] *= f0;
            oacc[nt][2] *= f1; oacc[nt][3] *= f1;
        }
        __syncwarp();

        #pragma unroll
        for (int ks = 0; ks < 8; ks++) {
            const int c = ks * 8 + c4;
            uint32_t af[4];
            af[0] = __float_as_uint(Pw[r4 * PQ + c]);
            af[1] = __float_as_uint(Pw[(r4 + 8) * PQ + c]);
            af[2] = __float_as_uint(Pw[r4 * PQ + c + 4]);
            af[3] = __float_as_uint(Pw[(r4 + 8) * PQ + c + 4]);
            #pragma unroll
            for (int nt = 0; nt < 8; nt++) {
                const int n = nt * 8 + r4;
                uint32_t bf[2];
                bf[0] = __float_as_uint(Vp[c * PV + n]);
                bf[1] = __float_as_uint(Vp[(c + 4) * PV + n]);
                mma_tf32(oacc[nt], af, bf);
            }
        }

        __syncthreads();
        if (kt + 2 <= qt) { issue_kv(cur, (kt + 2) * 64); cp_commit(); }
    }

    const float inv0 = 1.f / l0, inv1 = 1.f / l1;
    const int row0 = q0 + warp * 16 + r4;
    #pragma unroll
    for (int nt = 0; nt < 8; nt++) {
        const int col = h * HD + nt * 8 + 2 * c4;
        float2 o0, o1;
        o0.x = oacc[nt][0] * inv0; o0.y = oacc[nt][1] * inv0;
        o1.x = oacc[nt][2] * inv1; o1.y = oacc[nt][3] * inv1;
        *(float2*)(O + (size_t)(b * TD + row0) * CD + col)     = o0;
        *(float2*)(O + (size_t)(b * TD + row0 + 8) * CD + col) = o1;
    }
}

// ---------------------------------------------------------------------------
// Launch
// ---------------------------------------------------------------------------
extern "C" void kernel_launch(void* const* d_in, const int* in_sizes, int n_in,
                              void* d_out, int out_size)
{
    const float* x      = (const float*)d_in[0];
    const float* ln_a_g = (const float*)d_in[1];
    const float* ln_a_b = (const float*)d_in[2];
    const float* ln_b_g = (const float*)d_in[3];
    const float* ln_b_b = (const float*)d_in[4];
    const float* ln_c_g = (const float*)d_in[5];
    const float* ln_c_b = (const float*)d_in[6];
    const float* Wq = (const float*)d_in[7];  const float* bq = (const float*)d_in[8];
    const float* Wk = (const float*)d_in[9];  const float* bk = (const float*)d_in[10];
    const float* Wv = (const float*)d_in[11]; const float* bv = (const float*)d_in[12];
    const float* Wo = (const float*)d_in[13]; const float* bo = (const float*)d_in[14];
    const float* We = (const float*)d_in[15]; const float* be = (const float*)d_in[16];
    const float* Wd = (const float*)d_in[17]; const float* bd = (const float*)d_in[18];
    float* out = (float*)d_out;

    float *t, *q, *k, *v, *ctx, *x2, *h;
    cudaGetSymbolAddress((void**)&t,   g_t);
    cudaGetSymbolAddress((void**)&q,   g_q);
    cudaGetSymbolAddress((void**)&k,   g_k);
    cudaGetSymbolAddress((void**)&v,   g_v);
    cudaGetSymbolAddress((void**)&ctx, g_ctx);
    cudaGetSymbolAddress((void**)&x2,  g_x2);
    cudaGetSymbolAddress((void**)&h,   g_h);

    cudaFuncSetAttribute(attn_tc, cudaFuncAttributeMaxDynamicSharedMemorySize,
                         ATTN_SMEM);

    // 1. t = LN_b(LN_a(x))
    ln2_kernel<<<NT, 256>>>(x, ln_a_g, ln_a_b, ln_b_g, ln_b_b, t);

    // 2. QKV projections
    {
        dim3 grid(CD / BNT, NT / BMT);
        gemm_tc<<<grid, 256>>>(t, Wq, bq, nullptr, q, NT, CD, CD, 0);
        gemm_tc<<<grid, 256>>>(t, Wk, bk, nullptr, k, NT, CD, CD, 0);
        gemm_tc<<<grid, 256>>>(t, Wv, bv, nullptr, v, NT, CD, CD, 0);
    }

    // 3. causal attention
    {
        dim3 grid(TD / 64, BD * HN);
        attn_tc<<<grid, 128, ATTN_SMEM>>>(q, k, v, ctx);
    }

    // 4. x2 = x + ctx @ Wo + bo
    {
        dim3 grid(CD / BNT, NT / BMT);
        gemm_tc<<<grid, 256>>>(ctx, Wo, bo, x, x2, NT, CD, CD, 0);
    }

    // 5. t = LN_c(x2)
    ln1_kernel<<<NT, 256>>>(x2, ln_c_g, ln_c_b, t);

    // 6. h = silu(t @ We + be)
    {
        dim3 grid(DFFD / BNT, NT / BMT);
        gemm_tc<<<grid, 256>>>(t, We, be, nullptr, h, NT, DFFD, CD, 1);
    }

    // 7. out = x2 + h @ Wd + bd
    {
        dim3 grid(CD / BNT, NT / BMT);
        gemm_tc<<<grid, 256>>>(h, Wd, bd, x2, out, NT, CD, DFFD, 0);
    }
}